// round 4
// baseline (speedup 1.0000x reference)
#include <cuda_runtime.h>
#include <math.h>

#define NB   8
#define CIN  16
#define HH   32
#define WW   32
#define OC   64
#define RDIM 144       // 3*3*16
#define OH   30
#define OW   30

// Precomputed state (no allocation allowed)
__device__ float g_w[RDIM * OC];   // exp(k+5), natural [r][oc] layout
__device__ float g_koff[OC];       // bias - delta_x * sum_r k
__device__ float g_dw;             // delta_w

// Packed fp32x2 FMA (sm_100+): d = a*b + d lanewise
#define FMA2(d, a, b) \
    asm("fma.rn.f32x2 %0, %1, %2, %0;" : "+l"(d) : "l"(a), "l"(b))

// ---------------- prep: blocks 0..35 exponentiate weights, block 36 does koff ----------------
__global__ __launch_bounds__(256)
void prep_kernel(const float* __restrict__ k,
                 const float* __restrict__ bias,
                 const float* __restrict__ dxp,
                 const float* __restrict__ dwp) {
    const int b = blockIdx.x;
    const int t = threadIdx.x;
    if (b < 36) {
        int i = b * 256 + t;               // 36*256 = 9216 = RDIM*OC
        g_w[i] = expf(k[i] + 5.0f);
    } else {
        __shared__ float part[256];
        const int oc    = t & 63;
        const int chunk = t >> 6;          // 4 chunks of 36 r each
        float s = 0.0f;
        #pragma unroll
        for (int j = 0; j < 36; j++)
            s += k[(chunk * 36 + j) * OC + oc];
        part[t] = s;
        __syncthreads();
        if (t < OC) {
            float tot = part[t] + part[t + 64] + part[t + 128] + part[t + 192];
            g_koff[t] = bias[t] - dxp[0] * tot;
        }
        if (t == 0) g_dw = dwp[0];
    }
}

// ---------------- conv: block = 4 warps; warp = (row, oc-octet); lane = column ----------------
__global__ __launch_bounds__(128)
void conv_kernel(const float* __restrict__ x, float* __restrict__ out) {
    __shared__ float xc[CIN][4][WW];   // clamped x+5 slab: 8192 B
    __shared__ float srow[4][WW];      // per-(row,w) channel-sum of raw x: 512 B

    const int n    = blockIdx.y;
    const int r0   = blockIdx.x * 2;   // output/input row base
    const int t    = threadIdx.x;
    const int lane = t & 31;
    const int wid  = t >> 5;

    // --- Stage x slab: 4 rows x 32 cols, thread = (row, w), loop channels ---
    {
        const int srw = t >> 5;    // 0..3
        const int w   = t & 31;    // 0..31
        const float* xp = x + ((size_t)n * CIN * HH + (r0 + srw)) * WW + w;
        float s = 0.0f;
        #pragma unroll
        for (int c = 0; c < CIN; c++) {
            float v = xp[(size_t)c * HH * WW];
            s += v;
            xc[c][srw][w] = fmaxf(v + 5.0f, 1e-12f);
        }
        srow[srw][w] = s;
    }
    __syncthreads();

    const int rowsel = wid >> 1;                       // 0..1 (warp-uniform)
    const int ocbase = (blockIdx.z * 2 + (wid & 1)) * 8;  // warp-uniform

    if (lane < OW) {
        unsigned long long acc[4] = {0ull, 0ull, 0ull, 0ull};

        #pragma unroll
        for (int kh = 0; kh < 3; kh++)
        #pragma unroll
        for (int kw = 0; kw < 3; kw++)
        #pragma unroll
        for (int c = 0; c < CIN; c++) {
            const int r = (kh * 3 + kw) * CIN + c;
            const float xv = xc[c][rowsel + kh][lane + kw];   // conflict-free LDS.32
            unsigned long long xv2;
            asm("mov.b64 %0, {%1, %1};" : "=l"(xv2) : "r"(__float_as_uint(xv)));
            const ulonglong2* wp = (const ulonglong2*)(g_w + r * OC + ocbase); // uniform LDG.128 x2
            ulonglong2 wa = wp[0];
            ulonglong2 wb = wp[1];
            FMA2(acc[0], xv2, wa.x);
            FMA2(acc[1], xv2, wa.y);
            FMA2(acc[2], xv2, wb.x);
            FMA2(acc[3], xv2, wb.y);
        }

        // x_sum: 3x3 window over channel sums, times delta_w
        float xs = 0.0f;
        #pragma unroll
        for (int kh = 0; kh < 3; kh++)
            #pragma unroll
            for (int kw = 0; kw < 3; kw++)
                xs += srow[rowsel + kh][lane + kw];
        xs *= g_dw;

        const int row = r0 + rowsel;
        float* op = out + ((size_t)(n * OC + ocbase)) * (OH * OW) + row * OW + lane;
        #pragma unroll
        for (int q = 0; q < 4; q++) {
            float lo = __uint_as_float((unsigned)(acc[q] & 0xffffffffu));
            float hi = __uint_as_float((unsigned)(acc[q] >> 32));
            op[(size_t)(2 * q)     * (OH * OW)] = lo - xs + g_koff[ocbase + 2 * q];
            op[(size_t)(2 * q + 1) * (OH * OW)] = hi - xs + g_koff[ocbase + 2 * q + 1];
        }
    }
}

extern "C" void kernel_launch(void* const* d_in, const int* in_sizes, int n_in,
                              void* d_out, int out_size) {
    const float* x    = (const float*)d_in[0];
    const float* k    = (const float*)d_in[1];
    const float* bias = (const float*)d_in[2];
    const float* dx   = (const float*)d_in[3];
    const float* dw   = (const float*)d_in[4];
    float* out = (float*)d_out;

    prep_kernel<<<37, 256>>>(k, bias, dx, dw);
    dim3 grid(OH / 2, NB, 4);   // (15, 8, 4) = 480 blocks
    conv_kernel<<<grid, 128>>>(x, out);
}

// round 5
// speedup vs baseline: 2.2653x; 2.2653x over previous
#include <cuda_runtime.h>
#include <math.h>

#define NB   8
#define CIN  16
#define HH   32
#define WW   32
#define OC   64
#define RDIM 144
#define OH   30
#define OW   30

// Packed fp32x2 FMA (sm_100+): d = a*b + d lanewise
#define FMA2(d, a, b) \
    asm("fma.rn.f32x2 %0, %1, %2, %0;" : "+l"(d) : "l"(a), "l"(b))
#define PACK2(d, v) \
    asm("mov.b64 %0, {%1, %1};" : "=l"(d) : "r"(__float_as_uint(v)))

__global__ __launch_bounds__(128)
void fused_kernel(const float* __restrict__ x,
                  const float* __restrict__ k,
                  const float* __restrict__ bias,
                  const float* __restrict__ dxp,
                  const float* __restrict__ dwp,
                  float* __restrict__ out) {
    __shared__ float ws[RDIM][32];    // exp(k+5) slice: 18432 B
    __shared__ float xc[CIN][4][WW];  // clamped x+5 slab: 8192 B
    __shared__ float srow[4][WW];     // channel-sums of raw x: 512 B
    __shared__ float part[128];
    __shared__ float koff[32];
    __shared__ float sdw;

    const int n      = blockIdx.y;
    const int r0     = blockIdx.x * 2;       // output row base
    const int ocbase = blockIdx.z * 32;      // 0 or 32
    const int t      = threadIdx.x;
    const int lane   = t & 31;
    const int wid    = t >> 5;

    // --- Stage weight slice with fused exp: t = rsub*32 + oci ---
    {
        const int oci  = t & 31;
        const int rsub = t >> 5;
        #pragma unroll
        for (int rb = 0; rb < RDIM; rb += 4)
            ws[rb + rsub][oci] = expf(k[(rb + rsub) * OC + ocbase + oci] + 5.0f);
    }
    // --- Stage x slab: 4 input rows x 32 cols ---
    {
        const int srw = t >> 5, w = t & 31;
        const float* xp = x + ((size_t)n * CIN * HH + (r0 + srw)) * WW + w;
        float s = 0.0f;
        #pragma unroll
        for (int c = 0; c < CIN; c++) {
            float v = xp[(size_t)c * HH * WW];
            s += v;
            xc[c][srw][w] = fmaxf(v + 5.0f, 1e-12f);
        }
        srow[srw][w] = s;
    }
    // --- koff partials: t = quarter*32 + oci ---
    {
        const int oci = t & 31, q = t >> 5;
        float s = 0.0f;
        #pragma unroll
        for (int j = 0; j < 36; j++)
            s += k[(q * 36 + j) * OC + ocbase + oci];
        part[t] = s;
    }
    if (t == 0) sdw = dwp[0];
    __syncthreads();
    if (t < 32)
        koff[t] = bias[ocbase + t]
                - dxp[0] * (part[t] + part[t + 32] + part[t + 64] + part[t + 96]);
    __syncthreads();

    // --- Main loop: lane = rowbit*16 + colpair; warp = 8 oc ---
    const int cp   = lane & 15;          // col pair 0..15 (15 inactive)
    const int rowb = lane >> 4;          // 0..1
    const int ocg  = wid * 8;            // oc offset within 32 (warp-uniform)
    const int c0   = (cp < 15) ? 2 * cp : 28;  // clamped in-bounds load base
    const bool active = (cp < 15);

    unsigned long long acc[2][4];
    #pragma unroll
    for (int j = 0; j < 2; j++)
        #pragma unroll
        for (int q = 0; q < 4; q++) acc[j][q] = 0ull;

    #pragma unroll
    for (int kh = 0; kh < 3; kh++) {
        #pragma unroll 8
        for (int c = 0; c < CIN; c++) {
            const float2 xa = *(const float2*)&xc[c][rowb + kh][c0];
            const float2 xb = *(const float2*)&xc[c][rowb + kh][c0 + 2];
            unsigned long long p[4];
            PACK2(p[0], xa.x);
            PACK2(p[1], xa.y);
            PACK2(p[2], xb.x);
            PACK2(p[3], xb.y);
            #pragma unroll
            for (int kw = 0; kw < 3; kw++) {
                const ulonglong2* wp =
                    (const ulonglong2*)&ws[(kh * 3 + kw) * CIN + c][ocg];
                const ulonglong2 w01 = wp[0];   // oc 0-3
                const ulonglong2 w23 = wp[1];   // oc 4-7
                FMA2(acc[0][0], p[kw],     w01.x);
                FMA2(acc[0][1], p[kw],     w01.y);
                FMA2(acc[0][2], p[kw],     w23.x);
                FMA2(acc[0][3], p[kw],     w23.y);
                FMA2(acc[1][0], p[kw + 1], w01.x);
                FMA2(acc[1][1], p[kw + 1], w01.y);
                FMA2(acc[1][2], p[kw + 1], w23.x);
                FMA2(acc[1][3], p[kw + 1], w23.y);
            }
        }
    }

    if (active) {
        // x_sum terms for both columns
        float xs0 = 0.0f, xs1 = 0.0f;
        #pragma unroll
        for (int kh = 0; kh < 3; kh++)
            #pragma unroll
            for (int kw = 0; kw < 3; kw++) {
                xs0 += srow[rowb + kh][2 * cp + kw];
                xs1 += srow[rowb + kh][2 * cp + 1 + kw];
            }
        const float dwv = sdw;
        xs0 *= dwv; xs1 *= dwv;

        const int row = r0 + rowb;
        const int col = 2 * cp;
        float* op = out + ((size_t)(n * OC + ocbase + ocg)) * (OH * OW)
                  + row * OW + col;
        #pragma unroll
        for (int q = 0; q < 4; q++) {
            const float a0lo = __uint_as_float((unsigned)(acc[0][q] & 0xffffffffu));
            const float a0hi = __uint_as_float((unsigned)(acc[0][q] >> 32));
            const float a1lo = __uint_as_float((unsigned)(acc[1][q] & 0xffffffffu));
            const float a1hi = __uint_as_float((unsigned)(acc[1][q] >> 32));
            const float k0 = koff[ocg + 2 * q];
            const float k1 = koff[ocg + 2 * q + 1];
            float2 v0 = make_float2(a0lo - xs0 + k0, a1lo - xs1 + k0);
            float2 v1 = make_float2(a0hi - xs0 + k1, a1hi - xs1 + k1);
            *(float2*)(op + (size_t)(2 * q)     * (OH * OW)) = v0;
            *(float2*)(op + (size_t)(2 * q + 1) * (OH * OW)) = v1;
        }
    }
}

extern "C" void kernel_launch(void* const* d_in, const int* in_sizes, int n_in,
                              void* d_out, int out_size) {
    const float* x    = (const float*)d_in[0];
    const float* k    = (const float*)d_in[1];
    const float* bias = (const float*)d_in[2];
    const float* dx   = (const float*)d_in[3];
    const float* dw   = (const float*)d_in[4];
    float* out = (float*)d_out;

    dim3 grid(OH / 2, NB, 2);   // (15, 8, 2) = 240 blocks
    fused_kernel<<<grid, 128>>>(x, k, bias, dx, dw, out);
}